// round 2
// baseline (speedup 1.0000x reference)
#include <cuda_runtime.h>
#include <math.h>
#include <stdint.h>

// Problem constants
#define BB 8
#define TT 4096
#define NM 1024
#define HS 128
#define MROWS (BB * TT)          // 32768 flattened rows
#define NQT (TT / 64)            // 64 query tiles per batch

// Scratch (allocation-free rule: __device__ globals)
__device__ float g_k [MROWS * HS];   // raw projection (V)
__device__ float g_kr[MROWS * HS];   // RoPE'd projection (Q and K)

// ---------------------------------------------------------------------------
__device__ __forceinline__ float fast_exp2(float x) {
    float y;
    asm("ex2.approx.ftz.f32 %0, %1;" : "=f"(y) : "f"(x));
    return y;
}

// ---------------------------------------------------------------------------
// Kernel 1: k = x @ W_K^T fused with RoPE (position-independent thetas,
// replicating the reference's in-place slice-write semantics).
// Tile: 128(m) x 128(h) x BK=32, 256 threads, 8x8 register tiles.
// ---------------------------------------------------------------------------
__global__ __launch_bounds__(256) void proj_rope_kernel(
    const float* __restrict__ x, const float* __restrict__ W)
{
    __shared__ float As[32][132];   // As[k][m], padded
    __shared__ float Bs[32][132];   // Bs[k][h], padded

    const int tid = threadIdx.x;
    const int tx = tid & 15;
    const int ty = tid >> 4;
    const int m0 = blockIdx.x * 128;

    float acc[8][8];
    #pragma unroll
    for (int i = 0; i < 8; i++)
        #pragma unroll
        for (int j = 0; j < 8; j++) acc[i][j] = 0.f;

    for (int k0 = 0; k0 < NM; k0 += 32) {
        #pragma unroll
        for (int c = 0; c < 4; c++) {
            int linear = c * 1024 + tid * 4;
            int row = linear >> 5;
            int kc  = linear & 31;
            float4 v = *(const float4*)&x[(size_t)(m0 + row) * NM + k0 + kc];
            As[kc + 0][row] = v.x;
            As[kc + 1][row] = v.y;
            As[kc + 2][row] = v.z;
            As[kc + 3][row] = v.w;
        }
        #pragma unroll
        for (int c = 0; c < 4; c++) {
            int linear = c * 1024 + tid * 4;
            int row = linear >> 5;
            int kc  = linear & 31;
            float4 v = *(const float4*)&W[(size_t)row * NM + k0 + kc];
            Bs[kc + 0][row] = v.x;
            Bs[kc + 1][row] = v.y;
            Bs[kc + 2][row] = v.z;
            Bs[kc + 3][row] = v.w;
        }
        __syncthreads();

        #pragma unroll 4
        for (int kk = 0; kk < 32; kk++) {
            float a[8], b[8];
            float4 a0 = *(const float4*)&As[kk][ty * 8];
            float4 a1 = *(const float4*)&As[kk][ty * 8 + 4];
            a[0] = a0.x; a[1] = a0.y; a[2] = a0.z; a[3] = a0.w;
            a[4] = a1.x; a[5] = a1.y; a[6] = a1.z; a[7] = a1.w;
            #pragma unroll
            for (int g = 0; g < 4; g++) {
                float2 bv = *(const float2*)&Bs[kk][2 * tx + 32 * g];
                b[2 * g + 0] = bv.x;
                b[2 * g + 1] = bv.y;
            }
            #pragma unroll
            for (int i = 0; i < 8; i++)
                #pragma unroll
                for (int j = 0; j < 8; j++)
                    acc[i][j] += a[i] * b[j];
        }
        __syncthreads();
    }

    #pragma unroll
    for (int g = 0; g < 4; g++) {
        int p = tx + 16 * g;                         // pair index 0..63
        float theta = powf(10000.0f, -((float)p) / 64.0f);
        float sth, cth;
        sincosf(theta, &sth, &cth);
        #pragma unroll
        for (int i = 0; i < 8; i++) {
            int m = m0 + ty * 8 + i;
            float t1 = acc[i][2 * g + 0];
            float t2 = acc[i][2 * g + 1];
            size_t base = (size_t)m * HS + 2 * tx + 32 * g;
            float2 raw; raw.x = t1; raw.y = t2;
            *(float2*)&g_k[base] = raw;
            float ev = t1 * cth + t2 * sth;          // even' written first
            float od = -ev * sth + t2 * cth;         // odd reads updated even'
            float2 rot; rot.x = ev; rot.y = od;
            *(float2*)&g_kr[base] = rot;
        }
    }
}

// ---------------------------------------------------------------------------
// Kernel 2: causal flash attention, fp32.  Q = K = g_kr, V = g_k.
// BM=BN=64, d=128, 128 threads.  Each CTA processes TWO query tiles
// (q and 63-q) sequentially -> every CTA does exactly 65 tile-iterations,
// 256 CTAs total = one balanced wave at 2 CTAs/SM.
// ---------------------------------------------------------------------------
#define SM_Q 0
#define SM_K (64 * 128)
#define SM_V (2 * 64 * 128)
#define SM_P (3 * 64 * 128)
#define SMEM_ATTN_BYTES ((3 * 64 * 128 + 64 * 64) * 4)   // 114688 B

__device__ __forceinline__ void load_tile_sw(float* dst, const float* __restrict__ src, int tid) {
    // 64 rows x 128 floats, XOR swizzle on 16B quads.
    #pragma unroll
    for (int c = 0; c < 16; c++) {
        int linear = c * 512 + tid * 4;
        int row  = linear >> 7;
        int col4 = (linear & 127) >> 2;
        float4 v = *(const float4*)&src[linear];
        *(float4*)&dst[row * 128 + 4 * (col4 ^ (row & 7))] = v;
    }
}

__device__ __forceinline__ void load_tile_pl(float* dst, const float* __restrict__ src, int tid) {
    #pragma unroll
    for (int c = 0; c < 16; c++) {
        int linear = c * 512 + tid * 4;
        *(float4*)&dst[linear] = *(const float4*)&src[linear];
    }
}

__global__ __launch_bounds__(128, 2) void attn_kernel(float* __restrict__ out)
{
    extern __shared__ float sm[];
    float* Qs = sm + SM_Q;   // swizzled [64][128]
    float* Ks = sm + SM_K;   // swizzled [64][128]
    float* Vs = sm + SM_V;   // plain    [64][128]
    float* Ps = sm + SM_P;   // plain    [64][64]

    const int tid = threadIdx.x;
    const int tx  = tid & 15;     // 0..15
    const int ty  = tid >> 4;     // 0..7
    const int b   = blockIdx.y;

    const float* krot = g_kr + (size_t)b * TT * HS;
    const float* kraw = g_k  + (size_t)b * TT * HS;
    const float C = 1.4426950408889634f * 0.08838834764831845f; // log2(e)/sqrt(128)

    #pragma unroll 1
    for (int sel = 0; sel < 2; sel++) {
        const int qi = sel ? (NQT - 1 - blockIdx.x) : blockIdx.x;

        __syncthreads();            // Qs safe vs previous tile's readers
        load_tile_sw(Qs, krot + (size_t)qi * 64 * HS, tid);

        float o[8][8];
        float mrow[8], lsum[8];
        #pragma unroll
        for (int i = 0; i < 8; i++) {
            mrow[i] = -1e30f; lsum[i] = 0.f;
            #pragma unroll
            for (int j = 0; j < 8; j++) o[i][j] = 0.f;
        }

        const int nTiles = qi + 1;
        for (int jt = 0; jt < nTiles; jt++) {
            __syncthreads();        // protect Ks/Vs vs previous iteration
            load_tile_sw(Ks, krot + (size_t)jt * 64 * HS, tid);
            load_tile_pl(Vs, kraw + (size_t)jt * 64 * HS, tid);
            __syncthreads();

            // ---- S = Q K^T ----
            float s[8][4];
            #pragma unroll
            for (int i = 0; i < 8; i++)
                #pragma unroll
                for (int j = 0; j < 4; j++) s[i][j] = 0.f;

            #pragma unroll 2
            for (int k4 = 0; k4 < 32; k4++) {
                float qr[8][4];
                #pragma unroll
                for (int i = 0; i < 8; i++) {
                    float4 t = *(const float4*)&Qs[(ty * 8 + i) * 128 + 4 * (k4 ^ i)];
                    qr[i][0] = t.x; qr[i][1] = t.y; qr[i][2] = t.z; qr[i][3] = t.w;
                }
                float kr[4][4];
                #pragma unroll
                for (int j = 0; j < 4; j++) {
                    int c = tx + 16 * j;
                    float4 t = *(const float4*)&Ks[c * 128 + 4 * (k4 ^ (tx & 7))];
                    kr[j][0] = t.x; kr[j][1] = t.y; kr[j][2] = t.z; kr[j][3] = t.w;
                }
                #pragma unroll
                for (int i = 0; i < 8; i++)
                    #pragma unroll
                    for (int j = 0; j < 4; j++) {
                        s[i][j] += qr[i][0] * kr[j][0];
                        s[i][j] += qr[i][1] * kr[j][1];
                        s[i][j] += qr[i][2] * kr[j][2];
                        s[i][j] += qr[i][3] * kr[j][3];
                    }
            }

            // ---- causal mask on diagonal tile ----
            if (jt == qi) {
                #pragma unroll
                for (int i = 0; i < 8; i++)
                    #pragma unroll
                    for (int j = 0; j < 4; j++)
                        if (tx + 16 * j > ty * 8 + i) s[i][j] = -1e30f;
            }

            // ---- online softmax (row stats across the 16 tx lanes) ----
            #pragma unroll
            for (int i = 0; i < 8; i++) {
                float tm = fmaxf(fmaxf(s[i][0], s[i][1]), fmaxf(s[i][2], s[i][3]));
                #pragma unroll
                for (int off = 1; off < 16; off <<= 1)
                    tm = fmaxf(tm, __shfl_xor_sync(0xffffffffu, tm, off));
                float mn  = fmaxf(mrow[i], tm);
                float fac = fast_exp2((mrow[i] - mn) * C);
                mrow[i] = mn;
                float ts = 0.f;
                #pragma unroll
                for (int j = 0; j < 4; j++) {
                    float p = fast_exp2((s[i][j] - mn) * C);
                    ts += p;
                    Ps[(ty * 8 + i) * 64 + tx + 16 * j] = p;
                }
                #pragma unroll
                for (int off = 1; off < 16; off <<= 1)
                    ts += __shfl_xor_sync(0xffffffffu, ts, off);
                lsum[i] = lsum[i] * fac + ts;
                #pragma unroll
                for (int j = 0; j < 8; j++) o[i][j] *= fac;
            }
            __syncthreads();        // Ps visible

            // ---- O += P V ----
            #pragma unroll 2
            for (int n4 = 0; n4 < 16; n4++) {
                float pr[8][4];
                #pragma unroll
                for (int i = 0; i < 8; i++) {
                    float4 t = *(const float4*)&Ps[(ty * 8 + i) * 64 + n4 * 4];
                    pr[i][0] = t.x; pr[i][1] = t.y; pr[i][2] = t.z; pr[i][3] = t.w;
                }
                #pragma unroll
                for (int u = 0; u < 4; u++) {
                    int n = n4 * 4 + u;
                    float vv[8];
                    #pragma unroll
                    for (int j = 0; j < 8; j++) vv[j] = Vs[n * 128 + tx + 16 * j];
                    #pragma unroll
                    for (int i = 0; i < 8; i++)
                        #pragma unroll
                        for (int j = 0; j < 8; j++)
                            o[i][j] += pr[i][u] * vv[j];
                }
            }
        }

        // ---- epilogue: normalize and store ----
        #pragma unroll
        for (int i = 0; i < 8; i++) {
            float inv = 1.0f / lsum[i];
            size_t rowbase = ((size_t)b * TT + (size_t)qi * 64 + ty * 8 + i) * HS;
            #pragma unroll
            for (int j = 0; j < 8; j++)
                out[rowbase + tx + 16 * j] = o[i][j] * inv;
        }
    }
}

// ---------------------------------------------------------------------------
extern "C" void kernel_launch(void* const* d_in, const int* in_sizes, int n_in,
                              void* d_out, int out_size)
{
    const float* x = (const float*)d_in[0];
    const float* W = (const float*)d_in[1];
    // Defensive: x (33554432 elems) is the big one, W_K is 131072.
    if (n_in >= 2 && in_sizes[0] < in_sizes[1]) {
        x = (const float*)d_in[1];
        W = (const float*)d_in[0];
    }

    cudaFuncSetAttribute(attn_kernel,
                         cudaFuncAttributeMaxDynamicSharedMemorySize,
                         SMEM_ATTN_BYTES);

    proj_rope_kernel<<<MROWS / 128, 256>>>(x, W);
    attn_kernel<<<dim3(NQT / 2, BB), 128, SMEM_ATTN_BYTES>>>((float*)d_out);
}

// round 4
// speedup vs baseline: 2.6815x; 2.6815x over previous
#include <cuda_runtime.h>
#include <math.h>
#include <stdint.h>

// Problem constants
#define BB 8
#define TT 4096
#define NM 1024
#define HS 128
#define MROWS (BB * TT)
#define NQT (TT / 64)            // 64 query tiles (rows of 64) per batch

// Scratch
__device__ float g_k [MROWS * HS];   // raw projection (V), tf32-rounded
__device__ float g_kr[MROWS * HS];   // RoPE'd projection (Q,K), tf32-rounded

// ---------------------------------------------------------------------------
__device__ __forceinline__ float fast_exp2(float x) {
    float y;
    asm("ex2.approx.ftz.f32 %0, %1;" : "=f"(y) : "f"(x));
    return y;
}
__device__ __forceinline__ float f2tf(float x) {   // round-to-nearest tf32
    uint32_t r;
    asm("cvt.rna.tf32.f32 %0, %1;" : "=r"(r) : "f"(x));
    return __uint_as_float(r);
}
__device__ __forceinline__ void mma_tf32(float c[4],
                                         uint32_t a0, uint32_t a1, uint32_t a2, uint32_t a3,
                                         uint32_t b0, uint32_t b1) {
    asm volatile(
        "mma.sync.aligned.m16n8k8.row.col.f32.tf32.tf32.f32 "
        "{%0,%1,%2,%3}, {%4,%5,%6,%7}, {%8,%9}, {%0,%1,%2,%3};\n"
        : "+f"(c[0]), "+f"(c[1]), "+f"(c[2]), "+f"(c[3])
        : "r"(a0), "r"(a1), "r"(a2), "r"(a3), "r"(b0), "r"(b1));
}
#define FU(x) __float_as_uint(x)

// ---------------------------------------------------------------------------
// Kernel 1: k = x @ W_K^T (tf32 mma) fused with RoPE.
// BM=128 (8 warps x m16), N=128 (16 n-tiles), BK=32 staged.
// ---------------------------------------------------------------------------
#define SX 36
__global__ __launch_bounds__(256) void proj_rope_kernel(
    const float* __restrict__ x, const float* __restrict__ W)
{
    __shared__ float Xs[128 * SX];
    __shared__ float Ws[128 * SX];

    const int tid  = threadIdx.x;
    const int w    = tid >> 5;
    const int lane = tid & 31;
    const int g    = lane >> 2;
    const int tq   = lane & 3;
    const int m0   = blockIdx.x * 128;

    float o[16][4];
    #pragma unroll
    for (int nt = 0; nt < 16; nt++)
        #pragma unroll
        for (int r = 0; r < 4; r++) o[nt][r] = 0.f;

    for (int k0 = 0; k0 < NM; k0 += 32) {
        // stage tiles (tf32-rounded)
        #pragma unroll
        for (int pass = 0; pass < 4; pass++) {
            int linear = pass * 1024 + tid * 4;
            int row = linear >> 5;
            int c   = linear & 31;
            float4 v = *(const float4*)&x[(size_t)(m0 + row) * NM + k0 + c];
            Xs[row * SX + c + 0] = f2tf(v.x);
            Xs[row * SX + c + 1] = f2tf(v.y);
            Xs[row * SX + c + 2] = f2tf(v.z);
            Xs[row * SX + c + 3] = f2tf(v.w);
            float4 u = *(const float4*)&W[(size_t)row * NM + k0 + c];
            Ws[row * SX + c + 0] = f2tf(u.x);
            Ws[row * SX + c + 1] = f2tf(u.y);
            Ws[row * SX + c + 2] = f2tf(u.z);
            Ws[row * SX + c + 3] = f2tf(u.w);
        }
        __syncthreads();

        #pragma unroll
        for (int kk = 0; kk < 4; kk++) {
            uint32_t a0 = FU(Xs[(w * 16 + g    ) * SX + kk * 8 + tq    ]);
            uint32_t a1 = FU(Xs[(w * 16 + g + 8) * SX + kk * 8 + tq    ]);
            uint32_t a2 = FU(Xs[(w * 16 + g    ) * SX + kk * 8 + tq + 4]);
            uint32_t a3 = FU(Xs[(w * 16 + g + 8) * SX + kk * 8 + tq + 4]);
            #pragma unroll
            for (int nt = 0; nt < 16; nt++) {
                uint32_t b0 = FU(Ws[(nt * 8 + g) * SX + kk * 8 + tq    ]);
                uint32_t b1 = FU(Ws[(nt * 8 + g) * SX + kk * 8 + tq + 4]);
                mma_tf32(o[nt], a0, a1, a2, a3, b0, b1);
            }
        }
        __syncthreads();
    }

    // Epilogue: RoPE (position-independent thetas, in-place semantics), tf32-round.
    const float THSC = -0.20762050f; // -log2(10000)/64  (fixed constant)
    const int r0 = m0 + w * 16 + g;
    const int r1 = r0 + 8;
    #pragma unroll
    for (int nt = 0; nt < 16; nt++) {
        int p = nt * 4 + tq;                       // pair index 0..63
        float theta = fast_exp2((float)p * THSC);  // 10000^(-p/64)
        float sth, cth;
        __sincosf(theta, &sth, &cth);
        // row r0
        {
            float t1 = o[nt][0], t2 = o[nt][1];
            float2 raw; raw.x = f2tf(t1); raw.y = f2tf(t2);
            *(float2*)&g_k[(size_t)r0 * HS + nt * 8 + 2 * tq] = raw;
            float ev = t1 * cth + t2 * sth;
            float od = -ev * sth + t2 * cth;
            float2 rot; rot.x = f2tf(ev); rot.y = f2tf(od);
            *(float2*)&g_kr[(size_t)r0 * HS + nt * 8 + 2 * tq] = rot;
        }
        // row r1
        {
            float t1 = o[nt][2], t2 = o[nt][3];
            float2 raw; raw.x = f2tf(t1); raw.y = f2tf(t2);
            *(float2*)&g_k[(size_t)r1 * HS + nt * 8 + 2 * tq] = raw;
            float ev = t1 * cth + t2 * sth;
            float od = -ev * sth + t2 * cth;
            float2 rot; rot.x = f2tf(ev); rot.y = f2tf(od);
            *(float2*)&g_kr[(size_t)r1 * HS + nt * 8 + 2 * tq] = rot;
        }
    }
}

// ---------------------------------------------------------------------------
// Kernel 2: causal flash attention, tf32 mma.  Q = K = g_kr, V = g_k.
// BM=BN=64, 4 warps (warp = 16 rows).  Q fragments cached in registers,
// Ps smem aliases the dead Qs buffer.  Heavy-first grid order.
// Strides chosen for conflict-free fragment LDS:
//   Qs/Ks stride 132, Vs stride 136, Ps 76.
// ---------------------------------------------------------------------------
#define SQ 132
#define SV 136
#define SP 76
#define OFF_K 8448               // 64*132
#define OFF_V 16896              // 2*64*132
#define SMEM_ATTN_FLOATS (16896 + 64 * SV)   // 25600 floats = 102400 B
#define SMEM_ATTN_BYTES (SMEM_ATTN_FLOATS * 4)

__global__ __launch_bounds__(128, 2) void attn_kernel(float* __restrict__ out)
{
    extern __shared__ float sm[];
    float* Qs = sm;              // [64][132] during prologue
    float* Ps = sm;              // [64][76]  aliases Qs after frag extraction
    float* Ks = sm + OFF_K;      // [64][132]
    float* Vs = sm + OFF_V;      // [64][136]

    const int tid  = threadIdx.x;
    const int w    = tid >> 5;
    const int lane = tid & 31;
    const int g    = lane >> 2;
    const int tq   = lane & 3;
    const int qi   = (NQT - 1) - blockIdx.x;   // heavy tiles first
    const int b    = blockIdx.y;

    const float* krot = g_kr + (size_t)b * TT * HS;
    const float* kraw = g_k  + (size_t)b * TT * HS;
    const float C = 1.4426950408889634f * 0.08838834764831845f; // log2(e)/sqrt(128)

    // ---- load Q tile, extract fragments into registers ----
    {
        const float* qsrc = krot + (size_t)qi * 64 * HS;
        #pragma unroll
        for (int pass = 0; pass < 16; pass++) {
            int linear = pass * 512 + tid * 4;
            int row = linear >> 7;
            int c   = linear & 127;
            *(float4*)&Qs[row * SQ + c] = *(const float4*)&qsrc[linear];
        }
    }
    __syncthreads();

    uint32_t qa[16][4];
    #pragma unroll
    for (int kk = 0; kk < 16; kk++) {
        qa[kk][0] = FU(Qs[(w * 16 + g    ) * SQ + kk * 8 + tq    ]);
        qa[kk][1] = FU(Qs[(w * 16 + g + 8) * SQ + kk * 8 + tq    ]);
        qa[kk][2] = FU(Qs[(w * 16 + g    ) * SQ + kk * 8 + tq + 4]);
        qa[kk][3] = FU(Qs[(w * 16 + g + 8) * SQ + kk * 8 + tq + 4]);
    }

    float o[16][4];
    #pragma unroll
    for (int nt = 0; nt < 16; nt++)
        #pragma unroll
        for (int r = 0; r < 4; r++) o[nt][r] = 0.f;
    float mrow0 = -1e30f, mrow1 = -1e30f, l0 = 0.f, l1 = 0.f;

    for (int jt = 0; jt <= qi; jt++) {
        __syncthreads();   // previous iteration's K/V (and Ps) consumers done
        {
            const float* ks = krot + (size_t)jt * 64 * HS;
            const float* vs = kraw + (size_t)jt * 64 * HS;
            #pragma unroll
            for (int pass = 0; pass < 16; pass++) {
                int linear = pass * 512 + tid * 4;
                int row = linear >> 7;
                int c   = linear & 127;
                *(float4*)&Ks[row * SQ + c] = *(const float4*)&ks[linear];
                *(float4*)&Vs[row * SV + c] = *(const float4*)&vs[linear];
            }
        }
        __syncthreads();

        // ---- S = Q K^T ----
        float sc[8][4];
        #pragma unroll
        for (int nt = 0; nt < 8; nt++)
            #pragma unroll
            for (int r = 0; r < 4; r++) sc[nt][r] = 0.f;

        #pragma unroll
        for (int kk = 0; kk < 16; kk++) {
            #pragma unroll
            for (int nt = 0; nt < 8; nt++) {
                uint32_t b0 = FU(Ks[(nt * 8 + g) * SQ + kk * 8 + tq    ]);
                uint32_t b1 = FU(Ks[(nt * 8 + g) * SQ + kk * 8 + tq + 4]);
                mma_tf32(sc[nt], qa[kk][0], qa[kk][1], qa[kk][2], qa[kk][3], b0, b1);
            }
        }

        // ---- causal mask on diagonal tile ----
        if (jt == qi) {
            int r0 = w * 16 + g, r1 = r0 + 8;
            #pragma unroll
            for (int nt = 0; nt < 8; nt++) {
                int c0 = nt * 8 + 2 * tq, c1 = c0 + 1;
                if (c0 > r0) sc[nt][0] = -1e30f;
                if (c1 > r0) sc[nt][1] = -1e30f;
                if (c0 > r1) sc[nt][2] = -1e30f;
                if (c1 > r1) sc[nt][3] = -1e30f;
            }
        }

        // ---- online softmax (rows live in quads; reduce over tq lanes) ----
        float tm0 = -1e30f, tm1 = -1e30f;
        #pragma unroll
        for (int nt = 0; nt < 8; nt++) {
            tm0 = fmaxf(tm0, fmaxf(sc[nt][0], sc[nt][1]));
            tm1 = fmaxf(tm1, fmaxf(sc[nt][2], sc[nt][3]));
        }
        tm0 = fmaxf(tm0, __shfl_xor_sync(0xffffffffu, tm0, 1));
        tm0 = fmaxf(tm0, __shfl_xor_sync(0xffffffffu, tm0, 2));
        tm1 = fmaxf(tm1, __shfl_xor_sync(0xffffffffu, tm1, 1));
        tm1 = fmaxf(tm1, __shfl_xor_sync(0xffffffffu, tm1, 2));

        float mn0 = fmaxf(mrow0, tm0);
        float mn1 = fmaxf(mrow1, tm1);
        float fac0 = fast_exp2((mrow0 - mn0) * C);
        float fac1 = fast_exp2((mrow1 - mn1) * C);
        mrow0 = mn0; mrow1 = mn1;

        float ts0 = 0.f, ts1 = 0.f;
        #pragma unroll
        for (int nt = 0; nt < 8; nt++) {
            float p0 = f2tf(fast_exp2((sc[nt][0] - mn0) * C));
            float p1 = f2tf(fast_exp2((sc[nt][1] - mn0) * C));
            float p2 = f2tf(fast_exp2((sc[nt][2] - mn1) * C));
            float p3 = f2tf(fast_exp2((sc[nt][3] - mn1) * C));
            ts0 += p0 + p1; ts1 += p2 + p3;
            sc[nt][0] = p0; sc[nt][1] = p1; sc[nt][2] = p2; sc[nt][3] = p3;
        }
        ts0 += __shfl_xor_sync(0xffffffffu, ts0, 1);
        ts0 += __shfl_xor_sync(0xffffffffu, ts0, 2);
        ts1 += __shfl_xor_sync(0xffffffffu, ts1, 1);
        ts1 += __shfl_xor_sync(0xffffffffu, ts1, 2);
        l0 = l0 * fac0 + ts0;
        l1 = l1 * fac1 + ts1;

        #pragma unroll
        for (int nt = 0; nt < 16; nt++) {
            o[nt][0] *= fac0; o[nt][1] *= fac0;
            o[nt][2] *= fac1; o[nt][3] *= fac1;
        }

        // ---- store P (warp-private rows), then PV ----
        __syncwarp();
        #pragma unroll
        for (int nt = 0; nt < 8; nt++) {
            float2 lo; lo.x = sc[nt][0]; lo.y = sc[nt][1];
            float2 hi; hi.x = sc[nt][2]; hi.y = sc[nt][3];
            *(float2*)&Ps[(w * 16 + g    ) * SP + nt * 8 + 2 * tq] = lo;
            *(float2*)&Ps[(w * 16 + g + 8) * SP + nt * 8 + 2 * tq] = hi;
        }
        __syncwarp();

        #pragma unroll
        for (int kk = 0; kk < 8; kk++) {
            uint32_t pa0 = FU(Ps[(w * 16 + g    ) * SP + kk * 8 + tq    ]);
            uint32_t pa1 = FU(Ps[(w * 16 + g + 8) * SP + kk * 8 + tq    ]);
            uint32_t pa2 = FU(Ps[(w * 16 + g    ) * SP + kk * 8 + tq + 4]);
            uint32_t pa3 = FU(Ps[(w * 16 + g + 8) * SP + kk * 8 + tq + 4]);
            #pragma unroll
            for (int nt = 0; nt < 16; nt++) {
                uint32_t b0 = FU(Vs[(kk * 8 + tq    ) * SV + nt * 8 + g]);
                uint32_t b1 = FU(Vs[(kk * 8 + tq + 4) * SV + nt * 8 + g]);
                mma_tf32(o[nt], pa0, pa1, pa2, pa3, b0, b1);
            }
        }
    }

    // ---- epilogue ----
    float inv0 = 1.0f / l0;
    float inv1 = 1.0f / l1;
    size_t r0 = (size_t)b * TT + (size_t)qi * 64 + w * 16 + g;
    size_t r1 = r0 + 8;
    #pragma unroll
    for (int nt = 0; nt < 16; nt++) {
        float2 lo; lo.x = o[nt][0] * inv0; lo.y = o[nt][1] * inv0;
        float2 hi; hi.x = o[nt][2] * inv1; hi.y = o[nt][3] * inv1;
        *(float2*)&out[r0 * HS + nt * 8 + 2 * tq] = lo;
        *(float2*)&out[r1 * HS + nt * 8 + 2 * tq] = hi;
    }
}

// ---------------------------------------------------------------------------
extern "C" void kernel_launch(void* const* d_in, const int* in_sizes, int n_in,
                              void* d_out, int out_size)
{
    const float* x = (const float*)d_in[0];
    const float* W = (const float*)d_in[1];
    if (n_in >= 2 && in_sizes[0] < in_sizes[1]) {   // defensive order check
        x = (const float*)d_in[1];
        W = (const float*)d_in[0];
    }

    cudaFuncSetAttribute(attn_kernel,
                         cudaFuncAttributeMaxDynamicSharedMemorySize,
                         SMEM_ATTN_BYTES);

    proj_rope_kernel<<<MROWS / 128, 256>>>(x, W);
    attn_kernel<<<dim3(NQT, BB), 128, SMEM_ATTN_BYTES>>>((float*)d_out);
}